// round 1
// baseline (speedup 1.0000x reference)
#include <cuda_runtime.h>
#include <cuda_bf16.h>

// Problem constants (fixed by the dataset)
#define B_   4
#define T_   4096
#define DIN  1024
#define H_   16
#define D_   64
#define NCOL 2048            // H*D*2
#define BT   (B_*T_)         // 16384
#define BH   (B_*H_)         // 64
#define CH   128             // scan chunk length (t)
#define NC   (T_/CH)         // 32 chunks per (b,h)

// Scratch (device globals: allocation-free per harness rules)
__device__ float g_ev[BH * T_ * D_];     // e^s * relu(v), layout [b][h][t][d]  (64 MB)
__device__ float g_eu[BH * T_];          // e^s,           layout [b][h][t]
__device__ float g_csev[BH * NC * D_];   // chunk sums / exclusive offsets for ev
__device__ float g_cseu[BH * NC];        // chunk sums / exclusive offsets for eu

// ---------------------------------------------------------------------------
// K1: fused GEMM  C[t, h*128 + 2d+sel] = A[t,:] . W[:, h,d,sel]  + relu
//     + epilogue: s = q_h . relu(k),  p = exp(s), write p*relu(v) and p.
// Tile: 128 rows(t) x 128 cols (= one full head), TK=16, 256 threads, 8x8/thread
// ---------------------------------------------------------------------------
__global__ __launch_bounds__(256) void k1_gemm(const float* __restrict__ A,
                                               const float* __restrict__ W,
                                               const float* __restrict__ Q) {
    __shared__ float As[16][132];   // [k][m], padded to reduce STS conflicts
    __shared__ float Ws[16][128];   // [k][n]

    const int tid = threadIdx.x;
    const int tx = tid & 15;        // col group (8 cols each)
    const int ty = tid >> 4;        // row group (8 rows each)
    const int bx = blockIdx.x;
    const int h  = blockIdx.y;
    const int rowBase = bx * 128;

    // global-load assignments
    const int arow = tid >> 2;            // 0..63 (two passes of 64 rows)
    const int akc  = (tid & 3) * 4;       // k sub-col
    const int wkr  = tid >> 4;            // 0..15 (k row)
    const int wnc  = (tid & 15) * 4;      // n sub-col (two passes of 64)

    const float* Ablk = A + (rowBase + arow) * DIN + akc;
    const float* Wblk = W + wkr * NCOL + h * 128 + wnc;

    float acc[8][8];
#pragma unroll
    for (int r = 0; r < 8; r++)
#pragma unroll
        for (int j = 0; j < 8; j++) acc[r][j] = 0.f;

    // prologue: prefetch k0 = 0
    float4 aR0 = *(const float4*)(Ablk);
    float4 aR1 = *(const float4*)(Ablk + 64 * DIN);
    float4 wR0 = *(const float4*)(Wblk);
    float4 wR1 = *(const float4*)(Wblk + 64);

    for (int k0 = 0; k0 < DIN; k0 += 16) {
        // stage registers -> smem
        As[akc + 0][arow] = aR0.x;  As[akc + 1][arow] = aR0.y;
        As[akc + 2][arow] = aR0.z;  As[akc + 3][arow] = aR0.w;
        As[akc + 0][arow + 64] = aR1.x;  As[akc + 1][arow + 64] = aR1.y;
        As[akc + 2][arow + 64] = aR1.z;  As[akc + 3][arow + 64] = aR1.w;
        *(float4*)&Ws[wkr][wnc]      = wR0;
        *(float4*)&Ws[wkr][wnc + 64] = wR1;
        __syncthreads();

        // prefetch next tile while computing
        if (k0 + 16 < DIN) {
            aR0 = *(const float4*)(Ablk + (k0 + 16));
            aR1 = *(const float4*)(Ablk + (k0 + 16) + 64 * DIN);
            wR0 = *(const float4*)(Wblk + (k0 + 16) * NCOL);
            wR1 = *(const float4*)(Wblk + (k0 + 16) * NCOL + 64);
        }

#pragma unroll
        for (int kk = 0; kk < 16; kk++) {
            float a[8], b[8];
            *(float4*)&a[0] = *(const float4*)&As[kk][ty * 8];
            *(float4*)&a[4] = *(const float4*)&As[kk][ty * 8 + 4];
            *(float4*)&b[0] = *(const float4*)&Ws[kk][tx * 8];
            *(float4*)&b[4] = *(const float4*)&Ws[kk][tx * 8 + 4];
#pragma unroll
            for (int r = 0; r < 8; r++)
#pragma unroll
                for (int j = 0; j < 8; j++)
                    acc[r][j] = fmaf(a[r], b[j], acc[r][j]);
        }
        __syncthreads();
    }

    // Epilogue: cols for this thread are n = tx*8 + j.
    //   even j -> k at d = tx*4 + j/2 ; odd j -> v at d = tx*4 + (j-1)/2
    float qv[4];
#pragma unroll
    for (int jj = 0; jj < 4; jj++) qv[jj] = Q[h * 64 + tx * 4 + jj];

#pragma unroll
    for (int r = 0; r < 8; r++) {
        const int gRow = rowBase + ty * 8 + r;
        const int b = gRow >> 12;        // /4096
        const int t = gRow & 4095;
        float sp = 0.f;
        float vv[4];
#pragma unroll
        for (int jj = 0; jj < 4; jj++) {
            float kval = fmaxf(acc[r][2 * jj], 0.f);
            vv[jj]     = fmaxf(acc[r][2 * jj + 1], 0.f);
            sp = fmaf(qv[jj], kval, sp);
        }
        // reduce partial dot across the 16 tx lanes (same ty = same 16-lane segment)
#pragma unroll
        for (int o = 8; o; o >>= 1) sp += __shfl_xor_sync(0xffffffffu, sp, o, 16);

        const float p = __expf(sp);
        const int base = (b * H_ + h) * T_ + t;
        if (tx == 0) g_eu[base] = p;
        float4 w4 = make_float4(p * vv[0], p * vv[1], p * vv[2], p * vv[3]);
        *(float4*)&g_ev[base * 64 + tx * 4] = w4;
    }
}

// ---------------------------------------------------------------------------
// K2: per-chunk sums of ev (per d) and eu
// ---------------------------------------------------------------------------
__global__ void k2_chunksum() {
    const int idx = blockIdx.x;       // bh*NC + c
    const int bh = idx >> 5;
    const int c  = idx & (NC - 1);
    const int tid = threadIdx.x;      // 64 threads = d

    const float* evp = g_ev + (bh * T_ + c * CH) * 64;
    float s = 0.f;
    for (int t = 0; t < CH; t++) s += evp[t * 64 + tid];
    g_csev[(bh * NC + c) * 64 + tid] = s;

    const float* eup = g_eu + bh * T_ + c * CH;
    float su = 0.f;
    for (int t = tid; t < CH; t += 64) su += eup[t];
    __shared__ float sred[64];
    sred[tid] = su;
    __syncthreads();
    if (tid < 32) {
        float v2 = sred[tid] + sred[tid + 32];
#pragma unroll
        for (int o = 16; o; o >>= 1) v2 += __shfl_down_sync(0xffffffffu, v2, o);
        if (tid == 0) g_cseu[bh * NC + c] = v2;
    }
}

// ---------------------------------------------------------------------------
// K3: exclusive prefix over the NC chunk sums, per (b,h)
// ---------------------------------------------------------------------------
__global__ void k3_prefix() {
    const int bh = blockIdx.x;
    const int tid = threadIdx.x;      // 64 = d
    float run = 0.f;
    for (int c = 0; c < NC; c++) {
        const int i = (bh * NC + c) * 64 + tid;
        float tmp = g_csev[i];
        g_csev[i] = run;
        run += tmp;
    }
    if (tid == 0) {
        float ru = 0.f;
        for (int c = 0; c < NC; c++) {
            float tmp = g_cseu[bh * NC + c];
            g_cseu[bh * NC + c] = ru;
            ru += tmp;
        }
    }
}

// ---------------------------------------------------------------------------
// K4: within-chunk inclusive cumsum + divide; write h_t = W_t/U_t in place
// ---------------------------------------------------------------------------
__global__ void k4_apply() {
    const int idx = blockIdx.x;
    const int bh = idx >> 5;
    const int c  = idx & (NC - 1);
    const int tid = threadIdx.x;      // 64 = d

    float accw = g_csev[(bh * NC + c) * 64 + tid];
    float accu = g_cseu[bh * NC + c];
    float* evp = g_ev + (bh * T_ + c * CH) * 64;
    const float* eup = g_eu + bh * T_ + c * CH;
    for (int t = 0; t < CH; t++) {
        accu += eup[t];                       // broadcast load, same for all d
        accw += evp[t * 64 + tid];
        evp[t * 64 + tid] = __fdividef(accw, accu);
    }
}

// ---------------------------------------------------------------------------
// K5: out[b,t,d] = sum_h h[b,h,t,d]
// ---------------------------------------------------------------------------
__global__ void k5_out(float* __restrict__ out) {
    const int gid = blockIdx.x * 256 + threadIdx.x;   // < BT*64
    const int d  = gid & 63;
    const int bt = gid >> 6;
    const int b  = bt >> 12;
    const int t  = bt & 4095;
    float s = 0.f;
#pragma unroll
    for (int h = 0; h < H_; h++)
        s += g_ev[((b * H_ + h) * T_ + t) * 64 + d];
    out[gid] = s;
}

// ---------------------------------------------------------------------------
extern "C" void kernel_launch(void* const* d_in, const int* in_sizes, int n_in,
                              void* d_out, int out_size) {
    const float* A = (const float*)d_in[0];   // inputs   [4,4096,1024]
    const float* W = (const float*)d_in[1];   // kv_kernel[1024,16,64,2]
    const float* Q = (const float*)d_in[2];   // q_kernel [16,64]
    float* out = (float*)d_out;               // [4,4096,64]

    dim3 g1(BT / 128, H_);
    k1_gemm<<<g1, 256>>>(A, W, Q);
    k2_chunksum<<<BH * NC, 64>>>();
    k3_prefix<<<BH, 64>>>();
    k4_apply<<<BH * NC, 64>>>();
    k5_out<<<(BT * 64) / 256, 256>>>(out);
}

// round 3
// speedup vs baseline: 5.3204x; 5.3204x over previous
#include <cuda_runtime.h>
#include <cuda_fp16.h>
#include <mma.h>
#include <cstdint>

using namespace nvcuda;

// ---------------- problem constants ----------------
#define B_   4
#define T_   4096
#define DIN  1024
#define H_   16
#define D_   64
#define NCOL 2048            // H*D*2
#define BT   (B_*T_)         // 16384
#define BH   (B_*H_)         // 64
#define CH   128
#define NC   (T_/CH)         // 32

// ---------------- GEMM tile config ----------------
#define MT   128             // rows per CTA
#define NTILE 128            // cols per CTA = one head
#define KC   64              // k per stage
#define NSTG (DIN/KC)        // 16
#define PAD  24              // row stride = KC+PAD = 88 halves = 176B (16B aligned, conflict-free)
#define LDS_ (KC + PAD)      // 88
#define TILE_BYTES (MT * LDS_ * 2)      // 22528
#define STAGE_BYTES (2 * TILE_BYTES)    // A + W = 45056
#define SM_Q_OFF   (2 * STAGE_BYTES)    // 90112
#define SMEM_TOTAL (SM_Q_OFF + 512)     // 90624
#define CLD  132             // epilogue C row stride (floats)

// ---------------- device scratch ----------------
__device__ __half g_Ah[BT * DIN];
__device__ __half g_Wt[NCOL * DIN];   // transposed: [n][k]
__device__ float g_ev[BH * T_ * D_];
__device__ float g_eu[BH * T_];
__device__ float g_csev[BH * NC * D_];
__device__ float g_cseu[BH * NC];

// ---------------- helpers ----------------
__device__ __forceinline__ uint32_t smem_u32(const void* p) {
    uint32_t a;
    asm("{ .reg .u64 t; cvta.to.shared.u64 t, %1; cvt.u32.u64 %0, t; }" : "=r"(a) : "l"(p));
    return a;
}
#define CP_ASYNC16(dst, src) \
    asm volatile("cp.async.ca.shared.global [%0], [%1], 16;" :: "r"(dst), "l"(src))
#define CP_COMMIT() asm volatile("cp.async.commit_group;" ::: "memory")
#define CP_WAIT1()  asm volatile("cp.async.wait_group 1;" ::: "memory")
#define CP_WAIT0()  asm volatile("cp.async.wait_group 0;" ::: "memory")

// ---------------------------------------------------------------------------
// K0a: convert A (f32) -> fp16
// ---------------------------------------------------------------------------
__global__ void k0_convA(const float* __restrict__ A) {
    int i = (blockIdx.x * 256 + threadIdx.x) * 4;
    float4 v = *(const float4*)(A + i);
    __half2* o = (__half2*)(g_Ah + i);
    o[0] = __floats2half2_rn(v.x, v.y);
    o[1] = __floats2half2_rn(v.z, v.w);
}

// ---------------------------------------------------------------------------
// K0b: transpose + convert W (f32 [DIN][NCOL]) -> fp16 [NCOL][DIN]
// ---------------------------------------------------------------------------
__global__ void k0_convW(const float* __restrict__ W) {
    __shared__ float tile[32][33];
    int n0 = blockIdx.x * 32, k0 = blockIdx.y * 32;
#pragma unroll
    for (int j = 0; j < 32; j += 8)
        tile[threadIdx.y + j][threadIdx.x] = W[(k0 + threadIdx.y + j) * NCOL + n0 + threadIdx.x];
    __syncthreads();
#pragma unroll
    for (int j = 0; j < 32; j += 8) {
        float x = tile[threadIdx.x][threadIdx.y + j];
        g_Wt[(n0 + threadIdx.y + j) * DIN + k0 + threadIdx.x] = __float2half_rn(x);
    }
}

// ---------------------------------------------------------------------------
// K1: wmma fp16 GEMM (128x128 per CTA = 1 head x 128 t-rows) + fused epilogue
// ---------------------------------------------------------------------------
__global__ void __launch_bounds__(256, 2) k1_mma(const float* __restrict__ Q) {
    extern __shared__ char smem[];
    const uint32_t sb = smem_u32(smem);
    const int tid = threadIdx.x;
    const int wid = tid >> 5;
    const int h = blockIdx.x;             // head
    const int mtile = blockIdx.y;         // 0..127
    const int rowBase = mtile * MT;
    const int nBase = h * NTILE;

    float* qs = (float*)(smem + SM_Q_OFF);
    if (tid < 64) qs[tid] = Q[h * 64 + tid];

    // warp tile: 64(m) x 32(n); warp_m = wid&1, warp_n = wid>>1
    const int warp_m = wid & 1;
    const int warp_n = wid >> 1;

    wmma::fragment<wmma::accumulator, 16, 16, 16, float> acc[4][2];
#pragma unroll
    for (int i = 0; i < 4; i++)
#pragma unroll
        for (int j = 0; j < 2; j++) wmma::fill_fragment(acc[i][j], 0.f);

    // cp.async issue: 8 x 16B per thread per stage (4 for A, 4 for W)
    const int r_ = tid >> 3;          // 0..31, +32 per rep
    const int c_ = tid & 7;           // 16B chunk (8 halves)
    auto issue_stage = [&](int sbuf, int k0) {
        const uint32_t stg = sb + sbuf * STAGE_BYTES;
#pragma unroll
        for (int rep = 0; rep < 4; rep++) {
            const int r = r_ + rep * 32;
            const uint32_t so = (uint32_t)((r * LDS_ + c_ * 8) * 2);
            CP_ASYNC16(stg + so, g_Ah + (rowBase + r) * DIN + k0 + c_ * 8);
            CP_ASYNC16(stg + TILE_BYTES + so, g_Wt + (nBase + r) * DIN + k0 + c_ * 8);
        }
        CP_COMMIT();
    };

    issue_stage(0, 0);
    issue_stage(1, KC);

    for (int it = 0; it < NSTG; it++) {
        if (it >= NSTG - 2) { CP_WAIT0(); } else { CP_WAIT1(); }
        __syncthreads();
        const __half* As = (const __half*)(smem + (it & 1) * STAGE_BYTES);
        const __half* Ws = (const __half*)(smem + (it & 1) * STAGE_BYTES + TILE_BYTES);

#pragma unroll
        for (int ks = 0; ks < KC / 16; ks++) {
            wmma::fragment<wmma::matrix_a, 16, 16, 16, __half, wmma::row_major> af[4];
            wmma::fragment<wmma::matrix_b, 16, 16, 16, __half, wmma::col_major> bf[2];
#pragma unroll
            for (int i = 0; i < 4; i++)
                wmma::load_matrix_sync(af[i], As + (warp_m * 64 + i * 16) * LDS_ + ks * 16, LDS_);
#pragma unroll
            for (int j = 0; j < 2; j++)
                wmma::load_matrix_sync(bf[j], Ws + (warp_n * 32 + j * 16) * LDS_ + ks * 16, LDS_);
#pragma unroll
            for (int i = 0; i < 4; i++)
#pragma unroll
                for (int j = 0; j < 2; j++)
                    wmma::mma_sync(acc[i][j], af[i], bf[j], acc[i][j]);
        }
        __syncthreads();
        if (it + 2 < NSTG) issue_stage(it & 1, (it + 2) * KC);
    }

    // ---- store accumulators to smem C [128][CLD] ----
    float* Cs = (float*)smem;
#pragma unroll
    for (int i = 0; i < 4; i++)
#pragma unroll
        for (int j = 0; j < 2; j++)
            wmma::store_matrix_sync(Cs + (warp_m * 64 + i * 16) * CLD + warp_n * 32 + j * 16,
                                    acc[i][j], CLD, wmma::mem_row_major);
    __syncthreads();

    // ---- fused epilogue: thread = (row, d-half) ----
    {
        const int row = tid >> 1;
        const int half = tid & 1;          // d in [half*32, half*32+32)
        const int gRow = rowBase + row;
        const int b = gRow >> 12, t = gRow & 4095;
        const float* crow = Cs + row * CLD + half * 64;
        const float* q = qs + half * 32;

        float sp = 0.f;
        float vv[32];
#pragma unroll
        for (int d = 0; d < 32; d++) {
            float2 kv = *(const float2*)(crow + 2 * d);
            sp = fmaf(q[d], fmaxf(kv.x, 0.f), sp);
            vv[d] = fmaxf(kv.y, 0.f);
        }
        sp += __shfl_xor_sync(0xffffffffu, sp, 1);
        const float p = __expf(sp);
        const int base = (b * H_ + h) * T_ + t;
        if (half == 0) g_eu[base] = p;
        float4* dst = (float4*)(g_ev + base * 64 + half * 32);
#pragma unroll
        for (int i = 0; i < 8; i++)
            dst[i] = make_float4(p * vv[4 * i], p * vv[4 * i + 1],
                                 p * vv[4 * i + 2], p * vv[4 * i + 3]);
    }
}

// ---------------------------------------------------------------------------
// K2: per-chunk sums
// ---------------------------------------------------------------------------
__global__ void k2_chunksum() {
    const int idx = blockIdx.x;
    const int bh = idx >> 5;
    const int c  = idx & (NC - 1);
    const int tid = threadIdx.x;

    const float* evp = g_ev + (bh * T_ + c * CH) * 64;
    float s = 0.f;
#pragma unroll 8
    for (int t = 0; t < CH; t++) s += evp[t * 64 + tid];
    g_csev[(bh * NC + c) * 64 + tid] = s;

    const float* eup = g_eu + bh * T_ + c * CH;
    float su = 0.f;
    for (int t = tid; t < CH; t += 64) su += eup[t];
    __shared__ float sred[64];
    sred[tid] = su;
    __syncthreads();
    if (tid < 32) {
        float v2 = sred[tid] + sred[tid + 32];
#pragma unroll
        for (int o = 16; o; o >>= 1) v2 += __shfl_down_sync(0xffffffffu, v2, o);
        if (tid == 0) g_cseu[bh * NC + c] = v2;
    }
}

// ---------------------------------------------------------------------------
// K3: exclusive prefix over chunk sums
// ---------------------------------------------------------------------------
__global__ void k3_prefix() {
    const int bh = blockIdx.x;
    const int tid = threadIdx.x;
    float run = 0.f;
    for (int c = 0; c < NC; c++) {
        const int i = (bh * NC + c) * 64 + tid;
        float tmp = g_csev[i];
        g_csev[i] = run;
        run += tmp;
    }
    if (tid == 0) {
        float ru = 0.f;
        for (int c = 0; c < NC; c++) {
            float tmp = g_cseu[bh * NC + c];
            g_cseu[bh * NC + c] = ru;
            ru += tmp;
        }
    }
}

// ---------------------------------------------------------------------------
// K4: within-chunk cumsum + divide (in place)
// ---------------------------------------------------------------------------
__global__ void k4_apply() {
    const int idx = blockIdx.x;
    const int bh = idx >> 5;
    const int c  = idx & (NC - 1);
    const int tid = threadIdx.x;

    float accw = g_csev[(bh * NC + c) * 64 + tid];
    float accu = g_cseu[bh * NC + c];
    float* evp = g_ev + (bh * T_ + c * CH) * 64;
    const float* eup = g_eu + bh * T_ + c * CH;
#pragma unroll 8
    for (int t = 0; t < CH; t++) {
        accu += eup[t];
        accw += evp[t * 64 + tid];
        evp[t * 64 + tid] = __fdividef(accw, accu);
    }
}

// ---------------------------------------------------------------------------
// K5: sum over heads
// ---------------------------------------------------------------------------
__global__ void k5_out(float* __restrict__ out) {
    const int gid = blockIdx.x * 256 + threadIdx.x;
    const int d  = gid & 63;
    const int bt = gid >> 6;
    const int b  = bt >> 12;
    const int t  = bt & 4095;
    float s = 0.f;
#pragma unroll
    for (int h = 0; h < H_; h++)
        s += g_ev[((b * H_ + h) * T_ + t) * 64 + d];
    out[gid] = s;
}

// ---------------------------------------------------------------------------
extern "C" void kernel_launch(void* const* d_in, const int* in_sizes, int n_in,
                              void* d_out, int out_size) {
    const float* A = (const float*)d_in[0];   // inputs   [4,4096,1024]
    const float* W = (const float*)d_in[1];   // kv_kernel[1024,16,64,2]
    const float* Q = (const float*)d_in[2];   // q_kernel [16,64]
    float* out = (float*)d_out;

    cudaFuncSetAttribute(k1_mma, cudaFuncAttributeMaxDynamicSharedMemorySize, SMEM_TOTAL);

    k0_convA<<<BT * DIN / 1024, 256>>>(A);
    k0_convW<<<dim3(NCOL / 32, DIN / 32), dim3(32, 8)>>>(W);
    k1_mma<<<dim3(H_, BT / MT), 256, SMEM_TOTAL>>>(Q);
    k2_chunksum<<<BH * NC, 64>>>();
    k3_prefix<<<BH, 64>>>();
    k4_apply<<<BH * NC, 64>>>();
    k5_out<<<(BT * 64) / 256, 256>>>(out);
}